// round 7
// baseline (speedup 1.0000x reference)
#include <cuda_runtime.h>

#define NL 7
#define BATCH 524288
#define TPB 256
#define PPB (TPB * 2)            // poses per block = 512
#define GRID (BATCH / PPB)       // 1024
#define POSF (PPB * 3)           // floats per link in position staging = 1536

// One chain step for one pose. EXACT same fmaf expression tree as the known-good
// R2/R4 kernel (rel_err 2.3e-4 deterministic) — do not reorder.
__device__ __forceinline__ void fk_step(int l, float qvl, float4 f,
                                        float vx, float vy, float vz,
                                        float& px, float& py, float& pz, float& pw,
                                        float& tx, float& ty, float& tz)
{
    // ---- translation update: t += rotate(p, tf) ----
    float c1x = fmaf(py, vz, -pz * vy);
    float c1y = fmaf(pz, vx, -px * vz);
    float c1z = fmaf(px, vy, -py * vx);
    float c2x = fmaf(pw, c1x, fmaf(py, c1z, -pz * c1y));
    float c2y = fmaf(pw, c1y, fmaf(pz, c1x, -px * c1z));
    float c2z = fmaf(pw, c1z, fmaf(px, c1y, -py * c1x));
    tx = fmaf(2.f, c2x, tx + vx);
    ty = fmaf(2.f, c2y, ty + vy);
    tz = fmaf(2.f, c2z, tz + vz);

    // ---- m = p (x) qf[l] ----
    float mw = fmaf(pw, f.w, -fmaf(px, f.x, fmaf(py, f.y, pz * f.z)));
    float mx = fmaf(pw, f.x, fmaf(px, f.w, fmaf(py, f.z, -pz * f.y)));
    float my = fmaf(pw, f.y, fmaf(-px, f.z, fmaf(py, f.w, pz * f.x)));
    float mz = fmaf(pw, f.z, fmaf(px, f.y, fmaf(-py, f.x, pz * f.w)));

    float s, c;
    __sincosf(0.5f * qvl, &s, &c);

    if ((l & 1) == 0) {
        // axis z: qa = (0,0,s,c)
        pw = fmaf(mw, c, -mz * s);
        px = fmaf(mx, c,  my * s);
        py = fmaf(my, c, -mx * s);
        pz = fmaf(mw, s,  mz * c);
    } else {
        // axis y: qa = (0,s,0,c)
        pw = fmaf(mw, c, -my * s);
        px = fmaf(mx, c, -mz * s);
        py = fmaf(mw, s,  my * c);
        pz = fmaf(mz, c,  mx * s);
    }
}

__global__ __launch_bounds__(TPB, 3)
void fk_quat2_kernel(const float* __restrict__ q,
                     const float* __restrict__ rot_fixed,
                     const float* __restrict__ trans_fixed,
                     float* __restrict__ out)
{
    __shared__ float4 sQF[NL];
    __shared__ float  sTF[NL * 3];
    // q staging (14KB) and position staging (42KB) used at different times
    __shared__ __align__(16) union SBuf {
        float q[PPB * NL];        // 3584 floats
        float pos[NL * POSF];     // 10752 floats
    } sB;

    const int tid  = threadIdx.x;
    const int base = blockIdx.x * PPB;

    // ---- cooperative coalesced q load: 896 float4 ----
    {
        const float4* gq4 = (const float4*)(q + (size_t)base * NL);
        float4* sq4 = (float4*)sB.q;
        #pragma unroll
        for (int j = tid; j < (PPB * NL) / 4; j += TPB)
            sq4[j] = gq4[j];
    }

    // ---- fixed params -> quats/trans (same values/ops as known-good build) ----
    if (tid < NL) {
        const float* R = rot_fixed + tid * 9;
        float r00 = R[0], r01 = R[1], r02 = R[2];
        float r10 = R[3], r11 = R[4], r12 = R[5];
        float r20 = R[6], r21 = R[7], r22 = R[8];
        const float eps = 1e-9f;
        float qw = 0.5f * sqrtf(fmaxf(1.f + r00 + r11 + r22, eps));
        float qx = 0.5f * sqrtf(fmaxf(1.f + r00 - r11 - r22, eps));
        float qy = 0.5f * sqrtf(fmaxf(1.f - r00 + r11 - r22, eps));
        float qz = 0.5f * sqrtf(fmaxf(1.f - r00 - r11 + r22, eps));
        qx = copysignf(qx, r21 - r12);
        qy = copysignf(qy, r02 - r20);
        qz = copysignf(qz, r10 - r01);
        sQF[tid] = make_float4(qx, qy, qz, qw);
    }
    if (tid < NL * 3) sTF[tid] = trans_fixed[tid];
    __syncthreads();

    // ---- per-thread joint angles for both poses (stride-7 LDS, conflict-free) ----
    float qa[NL], qb[NL];
    #pragma unroll
    for (int i = 0; i < NL; i++) {
        qa[i] = sB.q[tid * NL + i];
        qb[i] = sB.q[(tid + TPB) * NL + i];
    }
    __syncthreads();   // q buffer now reusable for position staging

    // pose A state
    float apx = 0.f, apy = 0.f, apz = 0.f, apw = 1.f;
    float atx = 0.f, aty = 0.f, atz = 0.f;
    // pose B state
    float bpx = 0.f, bpy = 0.f, bpz = 0.f, bpw = 1.f;
    float btx = 0.f, bty = 0.f, btz = 0.f;

    const int b0 = base + tid;
    const int b1 = b0 + TPB;
    float4* qu_out = (float4*)(out + (size_t)NL * BATCH * 3);

    #pragma unroll
    for (int l = 0; l < NL; l++) {
        float4 f = sQF[l];
        float vx = sTF[l * 3 + 0], vy = sTF[l * 3 + 1], vz = sTF[l * 3 + 2];

        fk_step(l, qa[l], f, vx, vy, vz, apx, apy, apz, apw, atx, aty, atz);
        fk_step(l, qb[l], f, vx, vy, vz, bpx, bpy, bpz, bpw, btx, bty, btz);

        // ---- stage positions (stride-3 STS, conflict-free) ----
        {
            float* p0 = &sB.pos[l * POSF + tid * 3];
            p0[0] = atx; p0[1] = aty; p0[2] = atz;
            float* p1 = &sB.pos[l * POSF + (tid + TPB) * 3];
            p1[0] = btx; p1[1] = bty; p1[2] = btz;
        }

        // ---- canonical quats (w>=0), coalesced float4 stores ----
        {
            float g0 = (apw < 0.f) ? -1.f : 1.f;
            qu_out[(size_t)l * BATCH + b0] =
                make_float4(g0 * apx, g0 * apy, g0 * apz, g0 * apw);
            float g1 = (bpw < 0.f) ? -1.f : 1.f;
            qu_out[(size_t)l * BATCH + b1] =
                make_float4(g1 * bpx, g1 * bpy, g1 * bpz, g1 * bpw);
        }
    }

    __syncthreads();

    // ---- flush positions: per link 384 contiguous float4, fully coalesced ----
    const float4* sp4 = (const float4*)sB.pos;
    for (int j = tid; j < NL * (POSF / 4); j += TPB) {
        int l   = j / (POSF / 4);
        int idx = j % (POSF / 4);
        float4* gp4 = (float4*)(out + ((size_t)l * BATCH + base) * 3);
        gp4[idx] = sp4[j];
    }
}

extern "C" void kernel_launch(void* const* d_in, const int* in_sizes, int n_in,
                              void* d_out, int out_size) {
    const float* q           = (const float*)d_in[0];
    const float* rot_fixed   = (const float*)d_in[1];
    const float* trans_fixed = (const float*)d_in[2];
    float* out = (float*)d_out;

    fk_quat2_kernel<<<GRID, TPB>>>(q, rot_fixed, trans_fixed, out);
}

// round 8
// speedup vs baseline: 1.0702x; 1.0702x over previous
#include <cuda_runtime.h>

#define NL 7
#define BATCH 524288
#define TPB 256
#define GRID (BATCH / TPB)      // 2048
#define POSF (TPB * 3)          // floats per link in position staging = 768

// One chain step for one pose. EXACT same fmaf expression tree as the known-good
// R2/R4 kernel (rel_err 2.3156e-4 deterministic) — do not reorder.
__device__ __forceinline__ void fk_step(int l, float qvl, float4 f,
                                        float vx, float vy, float vz,
                                        float& px, float& py, float& pz, float& pw,
                                        float& tx, float& ty, float& tz)
{
    // ---- translation update: t += rotate(p, tf) ----
    float c1x = fmaf(py, vz, -pz * vy);
    float c1y = fmaf(pz, vx, -px * vz);
    float c1z = fmaf(px, vy, -py * vx);
    float c2x = fmaf(pw, c1x, fmaf(py, c1z, -pz * c1y));
    float c2y = fmaf(pw, c1y, fmaf(pz, c1x, -px * c1z));
    float c2z = fmaf(pw, c1z, fmaf(px, c1y, -py * c1x));
    tx = fmaf(2.f, c2x, tx + vx);
    ty = fmaf(2.f, c2y, ty + vy);
    tz = fmaf(2.f, c2z, tz + vz);

    // ---- m = p (x) qf[l] ----
    float mw = fmaf(pw, f.w, -fmaf(px, f.x, fmaf(py, f.y, pz * f.z)));
    float mx = fmaf(pw, f.x, fmaf(px, f.w, fmaf(py, f.z, -pz * f.y)));
    float my = fmaf(pw, f.y, fmaf(-px, f.z, fmaf(py, f.w, pz * f.x)));
    float mz = fmaf(pw, f.z, fmaf(px, f.y, fmaf(-py, f.x, pz * f.w)));

    float s, c;
    __sincosf(0.5f * qvl, &s, &c);

    if ((l & 1) == 0) {
        // axis z: qa = (0,0,s,c)
        pw = fmaf(mw, c, -mz * s);
        px = fmaf(mx, c,  my * s);
        py = fmaf(my, c, -mx * s);
        pz = fmaf(mw, s,  mz * c);
    } else {
        // axis y: qa = (0,s,0,c)
        pw = fmaf(mw, c, -my * s);
        px = fmaf(mx, c, -mz * s);
        py = fmaf(mw, s,  my * c);
        pz = fmaf(mz, c,  mx * s);
    }
}

__global__ __launch_bounds__(TPB)
void fk_quat_kernel(const float* __restrict__ q,
                    const float* __restrict__ rot_fixed,
                    const float* __restrict__ trans_fixed,
                    float* __restrict__ out)
{
    __shared__ float4 sQF[NL];
    __shared__ float  sTF[NL * 3];
    // q staging (7KB) and position staging (21KB) used at different times
    __shared__ __align__(16) union SBuf {
        float q[TPB * NL];        // 1792 floats
        float pos[NL * POSF];     // 5376 floats
    } sB;

    const int tid  = threadIdx.x;
    const int base = blockIdx.x * TPB;

    // ---- cooperative coalesced q load: 448 float4 ----
    {
        const float4* gq4 = (const float4*)(q + (size_t)base * NL);
        float4* sq4 = (float4*)sB.q;
        #pragma unroll
        for (int j = tid; j < (TPB * NL) / 4; j += TPB)
            sq4[j] = gq4[j];
    }

    // ---- fixed params -> quats/trans ----
    if (tid < NL) {
        const float* R = rot_fixed + tid * 9;
        float r00 = R[0], r01 = R[1], r02 = R[2];
        float r10 = R[3], r11 = R[4], r12 = R[5];
        float r20 = R[6], r21 = R[7], r22 = R[8];
        const float eps = 1e-9f;
        float qw = 0.5f * sqrtf(fmaxf(1.f + r00 + r11 + r22, eps));
        float qx = 0.5f * sqrtf(fmaxf(1.f + r00 - r11 - r22, eps));
        float qy = 0.5f * sqrtf(fmaxf(1.f - r00 + r11 - r22, eps));
        float qz = 0.5f * sqrtf(fmaxf(1.f - r00 - r11 + r22, eps));
        qx = copysignf(qx, r21 - r12);
        qy = copysignf(qy, r02 - r20);
        qz = copysignf(qz, r10 - r01);
        sQF[tid] = make_float4(qx, qy, qz, qw);
    }
    if (tid < NL * 3) sTF[tid] = trans_fixed[tid];
    __syncthreads();

    // ---- per-thread joint angles (stride-7 LDS, conflict-free) ----
    float qv[NL];
    #pragma unroll
    for (int i = 0; i < NL; i++) qv[i] = sB.q[tid * NL + i];
    __syncthreads();   // q buffer now reusable for position staging

    // Parent world pose: identity quaternion + zero translation
    float px = 0.f, py = 0.f, pz = 0.f, pw = 1.f;
    float tx = 0.f, ty = 0.f, tz = 0.f;

    const int b = base + tid;
    float4* qu_out = (float4*)(out + (size_t)NL * BATCH * 3);

    #pragma unroll
    for (int l = 0; l < NL; l++) {
        float4 f = sQF[l];
        float vx = sTF[l * 3 + 0], vy = sTF[l * 3 + 1], vz = sTF[l * 3 + 2];

        fk_step(l, qv[l], f, vx, vy, vz, px, py, pz, pw, tx, ty, tz);

        // ---- stage position (stride-3 STS, bank-conflict-free) ----
        float* p0 = &sB.pos[l * POSF + tid * 3];
        p0[0] = tx; p0[1] = ty; p0[2] = tz;

        // ---- canonical quaternion (w>=0), coalesced float4 store ----
        float sgn = (pw < 0.f) ? -1.f : 1.f;
        qu_out[(size_t)l * BATCH + b] =
            make_float4(sgn * px, sgn * py, sgn * pz, sgn * pw);
    }

    __syncthreads();

    // ---- flush positions: per link, 768 contiguous floats = 192 float4 ----
    const float4* sp4 = (const float4*)sB.pos;
    #pragma unroll
    for (int l = 0; l < NL; l++) {
        if (tid < POSF / 4) {   // 192 of 256 threads
            float4* gp4 = (float4*)(out + ((size_t)l * BATCH + base) * 3);
            gp4[tid] = sp4[l * (POSF / 4) + tid];
        }
    }
}

extern "C" void kernel_launch(void* const* d_in, const int* in_sizes, int n_in,
                              void* d_out, int out_size) {
    const float* q           = (const float*)d_in[0];
    const float* rot_fixed   = (const float*)d_in[1];
    const float* trans_fixed = (const float*)d_in[2];
    float* out = (float*)d_out;

    fk_quat_kernel<<<GRID, TPB>>>(q, rot_fixed, trans_fixed, out);
}

// round 9
// speedup vs baseline: 1.1860x; 1.1082x over previous
#include <cuda_runtime.h>

#define NL 7
#define BATCH 524288
#define TPB 256
#define GRID (BATCH / TPB)      // 2048
#define POSF (TPB * 3)          // floats per link in position staging = 768

// One chain step for one pose. EXACT same fmaf expression tree as the known-good
// R2/R4 kernel (rel_err 2.3156e-4 deterministic) — do not reorder.
__device__ __forceinline__ void fk_step(int l, float qvl, float4 f,
                                        float vx, float vy, float vz,
                                        float& px, float& py, float& pz, float& pw,
                                        float& tx, float& ty, float& tz)
{
    // ---- translation update: t += rotate(p, tf) ----
    float c1x = fmaf(py, vz, -pz * vy);
    float c1y = fmaf(pz, vx, -px * vz);
    float c1z = fmaf(px, vy, -py * vx);
    float c2x = fmaf(pw, c1x, fmaf(py, c1z, -pz * c1y));
    float c2y = fmaf(pw, c1y, fmaf(pz, c1x, -px * c1z));
    float c2z = fmaf(pw, c1z, fmaf(px, c1y, -py * c1x));
    tx = fmaf(2.f, c2x, tx + vx);
    ty = fmaf(2.f, c2y, ty + vy);
    tz = fmaf(2.f, c2z, tz + vz);

    // ---- m = p (x) qf[l] ----
    float mw = fmaf(pw, f.w, -fmaf(px, f.x, fmaf(py, f.y, pz * f.z)));
    float mx = fmaf(pw, f.x, fmaf(px, f.w, fmaf(py, f.z, -pz * f.y)));
    float my = fmaf(pw, f.y, fmaf(-px, f.z, fmaf(py, f.w, pz * f.x)));
    float mz = fmaf(pw, f.z, fmaf(px, f.y, fmaf(-py, f.x, pz * f.w)));

    float s, c;
    __sincosf(0.5f * qvl, &s, &c);

    if ((l & 1) == 0) {
        // axis z: qa = (0,0,s,c)
        pw = fmaf(mw, c, -mz * s);
        px = fmaf(mx, c,  my * s);
        py = fmaf(my, c, -mx * s);
        pz = fmaf(mw, s,  mz * c);
    } else {
        // axis y: qa = (0,s,0,c)
        pw = fmaf(mw, c, -my * s);
        px = fmaf(mx, c, -mz * s);
        py = fmaf(mw, s,  my * c);
        pz = fmaf(mz, c,  mx * s);
    }
}

__global__ __launch_bounds__(TPB)
void fk_quat_kernel(const float* __restrict__ q,
                    const float* __restrict__ rot_fixed,
                    const float* __restrict__ trans_fixed,
                    float* __restrict__ out)
{
    __shared__ float4 sQF[NL];
    __shared__ float  sTF[NL * 3];
    // q staging (7KB) and position staging (21KB) used at different times
    __shared__ __align__(16) union SBuf {
        float q[TPB * NL];        // 1792 floats
        float pos[NL * POSF];     // 5376 floats
    } sB;

    const int tid  = threadIdx.x;
    const int base = blockIdx.x * TPB;

    // ---- cooperative coalesced q load: 448 float4 (default policy: keep in L2) ----
    {
        const float4* gq4 = (const float4*)(q + (size_t)base * NL);
        float4* sq4 = (float4*)sB.q;
        #pragma unroll
        for (int j = tid; j < (TPB * NL) / 4; j += TPB)
            sq4[j] = gq4[j];
    }

    // ---- fixed params -> quats/trans ----
    if (tid < NL) {
        const float* R = rot_fixed + tid * 9;
        float r00 = R[0], r01 = R[1], r02 = R[2];
        float r10 = R[3], r11 = R[4], r12 = R[5];
        float r20 = R[6], r21 = R[7], r22 = R[8];
        const float eps = 1e-9f;
        float qw = 0.5f * sqrtf(fmaxf(1.f + r00 + r11 + r22, eps));
        float qx = 0.5f * sqrtf(fmaxf(1.f + r00 - r11 - r22, eps));
        float qy = 0.5f * sqrtf(fmaxf(1.f - r00 + r11 - r22, eps));
        float qz = 0.5f * sqrtf(fmaxf(1.f - r00 - r11 + r22, eps));
        qx = copysignf(qx, r21 - r12);
        qy = copysignf(qy, r02 - r20);
        qz = copysignf(qz, r10 - r01);
        sQF[tid] = make_float4(qx, qy, qz, qw);
    }
    if (tid < NL * 3) sTF[tid] = trans_fixed[tid];
    __syncthreads();

    // ---- per-thread joint angles (stride-7 LDS, conflict-free) ----
    float qv[NL];
    #pragma unroll
    for (int i = 0; i < NL; i++) qv[i] = sB.q[tid * NL + i];
    __syncthreads();   // q buffer now reusable for position staging

    // Parent world pose: identity quaternion + zero translation
    float px = 0.f, py = 0.f, pz = 0.f, pw = 1.f;
    float tx = 0.f, ty = 0.f, tz = 0.f;

    const int b = base + tid;
    float4* qu_out = (float4*)(out + (size_t)NL * BATCH * 3);

    #pragma unroll
    for (int l = 0; l < NL; l++) {
        float4 f = sQF[l];
        float vx = sTF[l * 3 + 0], vy = sTF[l * 3 + 1], vz = sTF[l * 3 + 2];

        fk_step(l, qv[l], f, vx, vy, vz, px, py, pz, pw, tx, ty, tz);

        // ---- stage position (stride-3 STS, bank-conflict-free) ----
        float* p0 = &sB.pos[l * POSF + tid * 3];
        p0[0] = tx; p0[1] = ty; p0[2] = tz;

        // ---- canonical quaternion (w>=0), streaming float4 store ----
        float sgn = (pw < 0.f) ? -1.f : 1.f;
        __stcs(&qu_out[(size_t)l * BATCH + b],
               make_float4(sgn * px, sgn * py, sgn * pz, sgn * pw));
    }

    __syncthreads();

    // ---- flush positions: per link, 768 contiguous floats = 192 float4 ----
    const float4* sp4 = (const float4*)sB.pos;
    #pragma unroll
    for (int l = 0; l < NL; l++) {
        if (tid < POSF / 4) {   // 192 of 256 threads
            float4* gp4 = (float4*)(out + ((size_t)l * BATCH + base) * 3);
            __stcs(&gp4[tid], sp4[l * (POSF / 4) + tid]);
        }
    }
}

extern "C" void kernel_launch(void* const* d_in, const int* in_sizes, int n_in,
                              void* d_out, int out_size) {
    const float* q           = (const float*)d_in[0];
    const float* rot_fixed   = (const float*)d_in[1];
    const float* trans_fixed = (const float*)d_in[2];
    float* out = (float*)d_out;

    fk_quat_kernel<<<GRID, TPB>>>(q, rot_fixed, trans_fixed, out);
}